// round 1
// baseline (speedup 1.0000x reference)
#include <cuda_runtime.h>
#include <cstdint>
#include <cstddef>

// GRU_13907104105002: bidirectional GRU (T=200,B=4096,I=3,H=32) + FC(C=1).
// Mapping: warp = (batch, direction), lane = hidden index.
// Lane i keeps h_i in a register and gate rows {i, 32+i, 64+i} of W_hh in
// registers as f32x2 pairs along the reduction dim. h_j broadcast via shfl,
// MACs via Blackwell packed fma.rn.f32x2 (FFMA2) -> halves fma-pipe work.
// C=1 lets us fold the FC into a per-step warp reduction; hidden states are
// never stored. Forward kernel writes out = fc_b + dot_f; backward kernel
// accumulates out += dot_b (sequential launches, no atomics).

#define TT 200
#define BN 4096
#define HH 32

using ull = unsigned long long;

__device__ __forceinline__ ull pack2(float a, float b) {
    ull r; asm("mov.b64 %0, {%1, %2};" : "=l"(r) : "f"(a), "f"(b)); return r;
}
__device__ __forceinline__ ull fma2(ull a, ull b, ull c) {
    ull d; asm("fma.rn.f32x2 %0, %1, %2, %3;" : "=l"(d) : "l"(a), "l"(b), "l"(c)); return d;
}
__device__ __forceinline__ float hsum2(ull a) {
    float lo, hi; asm("mov.b64 {%0, %1}, %2;" : "=f"(lo), "=f"(hi) : "l"(a)); return lo + hi;
}
__device__ __forceinline__ float sigm(float x) {
    return __fdividef(1.f, 1.f + __expf(-x));
}
__device__ __forceinline__ float tanh_(float x) {
    // robust at extremes: e->inf gives 1, e->0 gives -1
    float e = __expf(2.f * x);
    return 1.f - __fdividef(2.f, e + 1.f);
}

template <int DIR>
__global__ __launch_bounds__(128, 3)
void gru_dir(const float* __restrict__ x,
             const float* __restrict__ w_ih, const float* __restrict__ w_hh,
             const float* __restrict__ b_ih, const float* __restrict__ b_hh,
             const float* __restrict__ fc_w, const float* __restrict__ fc_b,
             float* __restrict__ out)
{
    const int lane = threadIdx.x & 31;
    const int b    = (blockIdx.x * blockDim.x + threadIdx.x) >> 5;  // 0..4095

    // Hidden-weight rows for this lane's three gates, as packed f32 pairs.
    // Row stride = 32 floats = 128B, so 8B alignment for ull loads holds.
    const ull* pr = reinterpret_cast<const ull*>(w_hh + (size_t)lane * HH);
    const ull* pz = reinterpret_cast<const ull*>(w_hh + (size_t)(HH + lane) * HH);
    const ull* pn = reinterpret_cast<const ull*>(w_hh + (size_t)(2 * HH + lane) * HH);
    ull wr[16], wz[16], wn[16];
#pragma unroll
    for (int k = 0; k < 16; k++) { wr[k] = pr[k]; wz[k] = pz[k]; wn[k] = pn[k]; }

    // Input-gate weights (I = 3)
    const float wxr0 = w_ih[lane * 3 + 0], wxr1 = w_ih[lane * 3 + 1], wxr2 = w_ih[lane * 3 + 2];
    const float wxz0 = w_ih[(HH + lane) * 3 + 0], wxz1 = w_ih[(HH + lane) * 3 + 1], wxz2 = w_ih[(HH + lane) * 3 + 2];
    const float wxn0 = w_ih[(2 * HH + lane) * 3 + 0], wxn1 = w_ih[(2 * HH + lane) * 3 + 1], wxn2 = w_ih[(2 * HH + lane) * 3 + 2];

    const float br  = b_ih[lane] + b_hh[lane];                    // r: biases fold into pre-act
    const float bz  = b_ih[HH + lane] + b_hh[HH + lane];          // z: same
    const float bxn = b_ih[2 * HH + lane];                        // n: input bias (outside r*)
    const float bhn = b_hh[2 * HH + lane];                        // n: hidden bias (inside r*)
    const float fcw = fc_w[(DIR == 0) ? lane : (HH + lane)];
    const float fcb = fc_b[0];

    float h = 0.f;
    for (int s = 0; s < TT; s++) {
        const int t = (DIR == 0) ? s : (TT - 1 - s);
        const float* xp = x + ((size_t)t * BN + b) * 3;
        const float x0 = xp[0], x1 = xp[1], x2 = xp[2];

        // hg = W_hh @ h  for this lane's three gate rows, packed pairs along j
        ull ar = 0ull, az = 0ull, an = 0ull;
#pragma unroll
        for (int k = 0; k < 16; k++) {
            float ha = __shfl_sync(0xffffffffu, h, 2 * k);
            float hb = __shfl_sync(0xffffffffu, h, 2 * k + 1);
            ull hp = pack2(ha, hb);
            ar = fma2(wr[k], hp, ar);
            az = fma2(wz[k], hp, az);
            an = fma2(wn[k], hp, an);
        }

        const float pre_r = hsum2(ar) + fmaf(wxr2, x2, fmaf(wxr1, x1, fmaf(wxr0, x0, br)));
        const float pre_z = hsum2(az) + fmaf(wxz2, x2, fmaf(wxz1, x1, fmaf(wxz0, x0, bz)));
        const float hn    = hsum2(an) + bhn;
        const float xn    = fmaf(wxn2, x2, fmaf(wxn1, x1, fmaf(wxn0, x0, bxn)));

        const float r = sigm(pre_r);
        const float z = sigm(pre_z);
        const float n = tanh_(fmaf(r, hn, xn));
        h = fmaf(z, h - n, n);  // (1-z)*n + z*h

        // FC (C=1): per-step warp reduction; off the recurrence critical path
        float v = h * fcw;
#pragma unroll
        for (int m = 16; m >= 1; m >>= 1) v += __shfl_xor_sync(0xffffffffu, v, m);
        if (lane == 0) {
            const size_t oi = (size_t)t * BN + b;
            if (DIR == 0) out[oi] = v + fcb;
            else          out[oi] += v;
        }
    }
}

extern "C" void kernel_launch(void* const* d_in, const int* in_sizes, int n_in,
                              void* d_out, int out_size)
{
    (void)in_sizes; (void)n_in; (void)out_size;
    const float* x      = (const float*)d_in[0];
    const float* w_ih_f = (const float*)d_in[1];
    const float* w_hh_f = (const float*)d_in[2];
    const float* b_ih_f = (const float*)d_in[3];
    const float* b_hh_f = (const float*)d_in[4];
    const float* w_ih_b = (const float*)d_in[5];
    const float* w_hh_b = (const float*)d_in[6];
    const float* b_ih_b = (const float*)d_in[7];
    const float* b_hh_b = (const float*)d_in[8];
    const float* fc_w   = (const float*)d_in[9];
    const float* fc_b   = (const float*)d_in[10];
    float* out = (float*)d_out;

    const dim3 grid(BN / 4);   // 4 warps per 128-thread block, warp = batch element
    const dim3 blk(128);
    gru_dir<0><<<grid, blk>>>(x, w_ih_f, w_hh_f, b_ih_f, b_hh_f, fc_w, fc_b, out);
    gru_dir<1><<<grid, blk>>>(x, w_ih_b, w_hh_b, b_ih_b, b_hh_b, fc_w, fc_b, out);
}

// round 2
// speedup vs baseline: 1.3626x; 1.3626x over previous
#include <cuda_runtime.h>
#include <cstddef>
#include <cstdint>

// GRU_13907104105002: bidirectional GRU (T=200,B=4096,I=3,H=32) + FC(C=1).
// One kernel runs BOTH directions concurrently (2048 blocks; dir = blockIdx>=1024).
// warp = (batch, dir), lane = hidden index. Lane i keeps h_i and W_hh gate rows
// {i,32+i,64+i} in registers as f32x2 pairs. h broadcast via per-warp SMEM
// (1 STS + 8 LDS.128 per step, zero syncs — single-warp program order) instead
// of 32 SHFLs. MACs via fma.rn.f32x2 (FFMA2). C=1 folds FC into a per-step
// warp butterfly reduction. fwd writes out = fc_b + dot_f; bwd writes dot_b to
// __device__ scratch; a float4 combine kernel adds them (no RMW in the loop).

#define TT 200
#define BN 4096
#define HH 32

using ull = unsigned long long;

__device__ float g_scr[TT * BN];  // 3.3 MB scratch for backward dots

__device__ __forceinline__ ull pack2(float a, float b) {
    ull r; asm("mov.b64 %0, {%1, %2};" : "=l"(r) : "f"(a), "f"(b)); return r;
}
__device__ __forceinline__ ull fma2(ull a, ull b, ull c) {
    ull d; asm("fma.rn.f32x2 %0, %1, %2, %3;" : "=l"(d) : "l"(a), "l"(b), "l"(c)); return d;
}
__device__ __forceinline__ ull add2(ull a, ull b) {
    ull d; asm("add.rn.f32x2 %0, %1, %2;" : "=l"(d) : "l"(a), "l"(b)); return d;
}
__device__ __forceinline__ float hsum2(ull a) {
    float lo, hi; asm("mov.b64 {%0, %1}, %2;" : "=f"(lo), "=f"(hi) : "l"(a)); return lo + hi;
}
__device__ __forceinline__ float sigm(float x) {
    return __fdividef(1.f, 1.f + __expf(-x));
}
__device__ __forceinline__ float tanh_(float x) {
    float e = __expf(2.f * x);
    return 1.f - __fdividef(2.f, e + 1.f);
}

__global__ __launch_bounds__(128, 3)
void gru_both(const float* __restrict__ x,
              const float* __restrict__ w_ih_f, const float* __restrict__ w_hh_f,
              const float* __restrict__ b_ih_f, const float* __restrict__ b_hh_f,
              const float* __restrict__ w_ih_b, const float* __restrict__ w_hh_b,
              const float* __restrict__ b_ih_b, const float* __restrict__ b_hh_b,
              const float* __restrict__ fc_w, const float* __restrict__ fc_b,
              float* __restrict__ out)
{
    __shared__ float hbuf[4 * HH];   // one 32-float h vector per warp

    const int lane = threadIdx.x & 31;
    const int w    = threadIdx.x >> 5;
    const int gw   = blockIdx.x * 4 + w;      // 0..8191
    const int dir  = gw >> 12;                // 0 fwd, 1 bwd
    const int b    = gw & (BN - 1);

    const float* w_ih = dir ? w_ih_b : w_ih_f;
    const float* w_hh = dir ? w_hh_b : w_hh_f;
    const float* b_ih = dir ? b_ih_b : b_ih_f;
    const float* b_hh = dir ? b_hh_b : b_hh_f;

    // SMEM addresses for this warp's h vector
    uint32_t sbase;
    asm("{ .reg .u64 t; cvta.to.shared.u64 t, %1; cvt.u32.u64 %0, t; }"
        : "=r"(sbase) : "l"((const void*)hbuf));
    const uint32_t hb      = sbase + (w << 7);
    const uint32_t st_addr = hb + (lane << 2);

    // Hidden-weight rows for this lane's gates, as packed f32 pairs (128B row stride)
    const ull* pr = reinterpret_cast<const ull*>(w_hh + (size_t)lane * HH);
    const ull* pz = reinterpret_cast<const ull*>(w_hh + (size_t)(HH + lane) * HH);
    const ull* pn = reinterpret_cast<const ull*>(w_hh + (size_t)(2 * HH + lane) * HH);
    ull wr[16], wz[16], wn[16];
#pragma unroll
    for (int k = 0; k < 16; k++) { wr[k] = pr[k]; wz[k] = pz[k]; wn[k] = pn[k]; }

    // Input-gate weights (I=3)
    const float wxr0 = w_ih[lane * 3 + 0], wxr1 = w_ih[lane * 3 + 1], wxr2 = w_ih[lane * 3 + 2];
    const float wxz0 = w_ih[(HH + lane) * 3 + 0], wxz1 = w_ih[(HH + lane) * 3 + 1], wxz2 = w_ih[(HH + lane) * 3 + 2];
    const float wxn0 = w_ih[(2 * HH + lane) * 3 + 0], wxn1 = w_ih[(2 * HH + lane) * 3 + 1], wxn2 = w_ih[(2 * HH + lane) * 3 + 2];

    const float br  = b_ih[lane] + b_hh[lane];
    const float bz  = b_ih[HH + lane] + b_hh[HH + lane];
    const float bxn = b_ih[2 * HH + lane];
    const float bhn = b_hh[2 * HH + lane];
    const float fcw = fc_w[dir * HH + lane];
    const float fcb = fc_b[0];

    // h = 0 in register and in smem
    float h = 0.f;
    asm volatile("st.shared.f32 [%0], %1;" :: "r"(st_addr), "f"(h) : "memory");

    // Prefetch x for first step
    int t0 = dir ? (TT - 1) : 0;
    const float* xp = x + ((size_t)t0 * BN + b) * 3;
    float x0 = xp[0], x1 = xp[1], x2 = xp[2];

    for (int s = 0; s < TT; s++) {
        const int t  = dir ? (TT - 1 - s) : s;
        const int tn = dir ? (t > 0 ? t - 1 : 0) : (t < TT - 1 ? t + 1 : TT - 1);
        const float* xq = x + ((size_t)tn * BN + b) * 3;
        const float nx0 = xq[0], nx1 = xq[1], nx2 = xq[2];   // prefetch next step

        // Input-gate contributions (independent of smem loads)
        const float xr = fmaf(wxr2, x2, fmaf(wxr1, x1, fmaf(wxr0, x0, br)));
        const float xz = fmaf(wxz2, x2, fmaf(wxz1, x1, fmaf(wxz0, x0, bz)));
        const float xn = fmaf(wxn2, x2, fmaf(wxn1, x1, fmaf(wxn0, x0, bxn)));

        // hg = W_hh @ h via smem broadcast; 2 chains per gate
        ull ar0 = 0, ar1 = 0, az0 = 0, az1 = 0, an0 = 0, an1 = 0;
#pragma unroll
        for (int q = 0; q < 8; q++) {
            float a0, a1, a2, a3;
            asm volatile("ld.shared.v4.f32 {%0,%1,%2,%3}, [%4];"
                         : "=f"(a0), "=f"(a1), "=f"(a2), "=f"(a3)
                         : "r"(hb + q * 16) : "memory");
            const ull p0 = pack2(a0, a1);
            const ull p1 = pack2(a2, a3);
            ar0 = fma2(wr[2 * q], p0, ar0);  ar1 = fma2(wr[2 * q + 1], p1, ar1);
            az0 = fma2(wz[2 * q], p0, az0);  az1 = fma2(wz[2 * q + 1], p1, az1);
            an0 = fma2(wn[2 * q], p0, an0);  an1 = fma2(wn[2 * q + 1], p1, an1);
        }

        const float pre_r = hsum2(add2(ar0, ar1)) + xr;
        const float pre_z = hsum2(add2(az0, az1)) + xz;
        const float hn    = hsum2(add2(an0, an1)) + bhn;

        const float r = sigm(pre_r);
        const float z = sigm(pre_z);
        const float n = tanh_(fmaf(r, hn, xn));
        h = fmaf(z, h - n, n);   // (1-z)*n + z*h

        asm volatile("st.shared.f32 [%0], %1;" :: "r"(st_addr), "f"(h) : "memory");

        // FC (C=1): warp reduction, off the recurrence critical path
        float v = h * fcw;
#pragma unroll
        for (int m = 16; m >= 1; m >>= 1) v += __shfl_xor_sync(0xffffffffu, v, m);
        if (lane == 0) {
            const size_t oi = (size_t)t * BN + b;
            if (dir == 0) out[oi] = v + fcb;
            else          g_scr[oi] = v;
        }

        x0 = nx0; x1 = nx1; x2 = nx2;
    }
}

__global__ __launch_bounds__(256)
void combine_add(float* __restrict__ out)
{
    const int i = blockIdx.x * blockDim.x + threadIdx.x;   // 0..204799 float4s
    float4* o = reinterpret_cast<float4*>(out);
    const float4* s = reinterpret_cast<const float4*>(g_scr);
    float4 a = o[i];
    const float4 c = s[i];
    a.x += c.x; a.y += c.y; a.z += c.z; a.w += c.w;
    o[i] = a;
}

extern "C" void kernel_launch(void* const* d_in, const int* in_sizes, int n_in,
                              void* d_out, int out_size)
{
    (void)in_sizes; (void)n_in; (void)out_size;
    const float* x      = (const float*)d_in[0];
    const float* w_ih_f = (const float*)d_in[1];
    const float* w_hh_f = (const float*)d_in[2];
    const float* b_ih_f = (const float*)d_in[3];
    const float* b_hh_f = (const float*)d_in[4];
    const float* w_ih_b = (const float*)d_in[5];
    const float* w_hh_b = (const float*)d_in[6];
    const float* b_ih_b = (const float*)d_in[7];
    const float* b_hh_b = (const float*)d_in[8];
    const float* fc_w   = (const float*)d_in[9];
    const float* fc_b   = (const float*)d_in[10];
    float* out = (float*)d_out;

    gru_both<<<2048, 128>>>(x, w_ih_f, w_hh_f, b_ih_f, b_hh_f,
                            w_ih_b, w_hh_b, b_ih_b, b_hh_b, fc_w, fc_b, out);
    combine_add<<<(TT * BN / 4) / 256, 256>>>(out);   // 800 blocks
}